// round 15
// baseline (speedup 1.0000x reference)
#include <cuda_runtime.h>
#include <cuda_fp16.h>

// ---------------- problem constants ----------------
#define NCAND   65536
#define HID     1024
#define BOARD2  361
#define CPOL    256
#define KCAND   64

// ---------------- GEMM tiling (fp16 mma.sync m16n8k16 + ldmatrix) ----------------
#define BM 128
#define BN 128
#define BK 32            // two k16 mma steps per chunk
#define STAGES 5         // pipeline depth
#define THREADS 128
#define SA_STRIDE 40     // halves; 80B row -> LDSM conflict-free
#define SB_STRIDE 40
#define SA_BUF (BM*SA_STRIDE)            // 5120 halves
#define SB_BUF (BN*SB_STRIDE)            // 5120 halves
#define STAGE_HALVES (SA_BUF + SB_BUF)   // 10240
#define SMEM_BYTES (STAGES*STAGE_HALVES*2)   // 102400 (x2 CTAs = 200KB < 228KB)
#define SMEM1_BYTES (2*STAGE_HALVES*2)       // GEMM1: 2 stages = 40960
#define ACC_STRIDE 136                        // staging stride (halves); cf-free writes

// merged-prep block ranges (256 threads each)
#define PRE_PFM   0                       // 256 blocks: pfm transpose + pool + b1 copy
#define PRE_CAND  (PRE_PFM + CPOL)        // 4096 blocks: cand fp16 convert (vec4)
#define PRE_WT    (PRE_CAND + 4096)       // 1600 blocks: W2/W1c/Pw transposes
#define PRE_POS   (PRE_WT + 1600)         // 256 blocks: pos decode + out init
#define PRE_TOTAL (PRE_POS + 256)         // 6208

// ---------------- device scratch ----------------
__device__ float g_pool[CPOL];
__device__ float g_bias1[HID];
__device__ __align__(16) __half g_pfmTh[384*CPOL];  // fp16 pfm^T [p][c], rows 361+ stay zero
__device__ __align__(16) __half g_Pw[2048*CPOL];    // P-GEMM B [n][c]
__device__ __align__(16) __half g_P1h[BOARD2*HID];  // fp16(P1 + bias1)
__device__ __align__(16) __half g_P2h[BOARD2*HID];  // fp16(P2)
__device__ int   g_go[NCAND];
__device__ int   g_to[NCAND];
__device__ __align__(16) __half g_candh[NCAND*KCAND];     // fp16 cand feats [m][64]
__device__ __align__(16) __half g_W1ch[HID*KCAND];        // fp16 W1[768:832]^T [n][k]
__device__ __align__(16) __half g_W2h[HID*HID];           // fp16 W2^T          [n][k]
__device__ __align__(16) __half g_h1[(size_t)NCAND*HID];  // layer-1 activations fp16

// ---------------- helpers ----------------
__device__ __forceinline__ void cpa16(const void* smem_dst, const void* gmem_src) {
    unsigned sa;
    asm("{ .reg .u64 t; cvta.to.shared.u64 t, %1; cvt.u32.u64 %0, t; }"
        : "=r"(sa) : "l"(smem_dst));
    asm volatile("cp.async.cg.shared.global [%0], [%1], 16;" :: "r"(sa), "l"(gmem_src));
}
#define CP_COMMIT() asm volatile("cp.async.commit_group;")
template<int N>
__device__ __forceinline__ void cp_wait() {
    asm volatile("cp.async.wait_group %0;" :: "n"(N));
}

__device__ __forceinline__ void ldsm4(unsigned& r0, unsigned& r1, unsigned& r2, unsigned& r3,
                                      const __half* p) {
    unsigned sa;
    asm("{ .reg .u64 t; cvta.to.shared.u64 t, %1; cvt.u32.u64 %0, t; }"
        : "=r"(sa) : "l"(p));
    asm volatile("ldmatrix.sync.aligned.m8n8.x4.shared.b16 {%0,%1,%2,%3}, [%4];"
        : "=r"(r0), "=r"(r1), "=r"(r2), "=r"(r3) : "r"(sa));
}

__device__ __forceinline__ void mma16(float* c, const unsigned* a, const unsigned* b) {
    asm volatile(
        "mma.sync.aligned.m16n8k16.row.col.f32.f16.f16.f32 "
        "{%0,%1,%2,%3}, {%4,%5,%6,%7}, {%8,%9}, {%0,%1,%2,%3};"
        : "+f"(c[0]), "+f"(c[1]), "+f"(c[2]), "+f"(c[3])
        : "r"(a[0]), "r"(a[1]), "r"(a[2]), "r"(a[3]), "r"(b[0]), "r"(b[1]));
}

// fp16x2 + table1 + table2 in fp32, relu, repack
__device__ __forceinline__ unsigned addrelu2(unsigned a, unsigned p1, unsigned p2) {
    float2 af = __half22float2(*(__half2*)&a);
    float2 f1 = __half22float2(*(__half2*)&p1);
    float2 f2 = __half22float2(*(__half2*)&p2);
    __half2 r = __floats2half2_rn(fmaxf(af.x + f1.x + f2.x, 0.f),
                                  fmaxf(af.y + f1.y + f2.y, 0.f));
    return *(unsigned*)&r;
}

// ---------------- merged prep kernel ----------------
__global__ __launch_bounds__(256) void k_pre(
    const float* __restrict__ pfm, const float* __restrict__ b1,
    const float* __restrict__ cand, float* __restrict__ out,
    const float* __restrict__ b3,
    const float* __restrict__ W2, const float* __restrict__ W1)
{
    __shared__ float sh[32*33];
    const int bx = blockIdx.x;
    const int tid = threadIdx.x;

    if (bx < PRE_CAND) {
        const int c = bx;
        if (tid < 4) g_bias1[c*4 + tid] = b1[c*4 + tid];
        float s = 0.f;
        for (int p = tid; p < BOARD2; p += 256) {
            float v = pfm[c*BOARD2 + p];
            g_pfmTh[p*CPOL + c] = __float2half_rn(v);
            s += v;
        }
        sh[tid] = s; __syncthreads();
        for (int o = 128; o > 0; o >>= 1) {
            if (tid < o) sh[tid] += sh[tid + o];
            __syncthreads();
        }
        if (tid == 0) g_pool[c] = sh[0] / 361.0f;
    } else if (bx < PRE_WT) {
        const int i4 = (bx - PRE_CAND)*256 + tid;
        float4 v = *(const float4*)(cand + (size_t)i4*4);
        __half2 h0 = __floats2half2_rn(v.x, v.y);
        __half2 h1 = __floats2half2_rn(v.z, v.w);
        uint2 o2;
        o2.x = *(unsigned*)&h0;
        o2.y = *(unsigned*)&h1;
        *(uint2*)(g_candh + (size_t)i4*4) = o2;
    } else if (bx < PRE_POS) {
        float (*t)[33] = (float(*)[33])sh;
        const int b2i = bx - PRE_WT;
        const int gx = b2i & 31, gy = b2i >> 5;
        const int bxn = gx*32;
        const int x = tid & 31, y = tid >> 5;
        if (gy < 32) {
            int by = gy*32;
            for (int i = y; i < 32; i += 8)
                t[i][x] = W2[(size_t)(by+i)*HID + bxn + x];
            __syncthreads();
            for (int i = y; i < 32; i += 8)
                g_W2h[(size_t)(bxn+i)*HID + by + x] = __float2half_rn(t[x][i]);
        } else if (gy < 34) {
            int kb = (gy - 32)*32;
            for (int i = y; i < 32; i += 8)
                t[i][x] = W1[(size_t)(768+kb+i)*HID + bxn + x];
            __syncthreads();
            for (int i = y; i < 32; i += 8)
                g_W1ch[(size_t)(bxn+i)*KCAND + kb + x] = __float2half_rn(t[x][i]);
        } else if (gy < 42) {
            int kb = (gy - 34)*32;
            for (int i = y; i < 32; i += 8)
                t[i][x] = W1[(size_t)(kb+i)*HID + bxn + x];
            __syncthreads();
            for (int i = y; i < 32; i += 8)
                g_Pw[(size_t)(bxn+i)*CPOL + kb + x] = __float2half_rn(t[x][i]);
        } else {
            int kb = (gy - 42)*32;
            for (int i = y; i < 32; i += 8)
                t[i][x] = W1[(size_t)(256+kb+i)*HID + bxn + x];
            __syncthreads();
            for (int i = y; i < 32; i += 8)
                g_Pw[(size_t)(1024+bxn+i)*CPOL + kb + x] = __float2half_rn(t[x][i]);
        }
    } else {
        const int i = (bx - PRE_POS)*256 + tid;
        const float* f = cand + (size_t)i*KCAND;
        int gr = min(max((int)(f[5]*18.f), 0), 18);
        int gc = min(max((int)(f[6]*18.f), 0), 18);
        int tr = min(max((int)(f[7]*18.f), 0), 18);
        int tc = min(max((int)(f[8]*18.f), 0), 18);
        g_go[i] = gr*19 + gc;
        g_to[i] = tr*19 + tc;
        out[i] = b3[0];
    }
}

// bias1 += pool @ W1[512:768]   (split-k x32, atomic; fp32, exact)
__global__ void k_bias1(const float* __restrict__ W1) {
    int o  = blockIdx.x*128 + threadIdx.x;
    int c0 = blockIdx.y*8;
    float s = 0.f;
    #pragma unroll
    for (int c = c0; c < c0 + 8; c++)
        s += g_pool[c] * W1[(size_t)(512+c)*HID + o];
    atomicAdd(&g_bias1[o], s);
}

// ---------------- shared mainloop pieces ----------------
struct FragCtx {
    int aRowL, aKL, bNL, bKL, wm, wn;
};

__device__ __forceinline__ void compute_chunk(const __half* sA, const __half* sB,
                                              float acc[4][8][4], const FragCtx& fc) {
    const __half* pA = sA + (fc.wm*64 + fc.aRowL)*SA_STRIDE + fc.aKL;
    const __half* pB = sB + (fc.wn*64 + fc.bNL)*SB_STRIDE + fc.bKL;
    #pragma unroll
    for (int ks = 0; ks < 2; ks++) {
        const int kofs = ks*16;
        unsigned a[4][4], b[8][2];
        #pragma unroll
        for (int mt = 0; mt < 4; mt++)
            ldsm4(a[mt][0], a[mt][1], a[mt][2], a[mt][3],
                  pA + mt*16*SA_STRIDE + kofs);
        #pragma unroll
        for (int np = 0; np < 4; np++)
            ldsm4(b[2*np][0], b[2*np][1], b[2*np+1][0], b[2*np+1][1],
                  pB + np*16*SB_STRIDE + kofs);
        #pragma unroll
        for (int mt = 0; mt < 4; mt++)
            #pragma unroll
            for (int nt = 0; nt < 8; nt++)
                mma16(acc[mt][nt], a[mt], b[nt]);
    }
}

// pipelined mainloop shared by k_pwg / k_gemm2
template<int NCK>
__device__ __forceinline__ void run_pipeline(
    __half* sm, const __half* __restrict__ Ag, const __half* __restrict__ Bg,
    int lda, int row0, int col0, int tid, float acc[4][8][4], const FragCtx& fc)
{
    auto issue = [&](int ck, int s) {
        __half* sA = sm + s*STAGE_HALVES;
        __half* sB = sA + SA_BUF;
        const int k0 = ck * BK;
        #pragma unroll
        for (int i = 0; i < 4; i++) {
            int idx = tid + i*THREADS;
            int r = idx >> 2, c4 = idx & 3;
            cpa16(sA + r*SA_STRIDE + c4*8,
                  Ag + (size_t)(row0 + r)*lda + k0 + c4*8);
        }
        #pragma unroll
        for (int i = 0; i < 4; i++) {
            int idx = tid + i*THREADS;
            int r = idx >> 2, c4 = idx & 3;
            cpa16(sB + r*SB_STRIDE + c4*8,
                  Bg + (size_t)(col0 + r)*lda + k0 + c4*8);
        }
        CP_COMMIT();
    };

    #pragma unroll
    for (int s = 0; s < STAGES-1; s++) issue(s, s);

    for (int ck = 0; ck < NCK; ck++) {
        const int buf = ck % STAGES;
        const int rem = NCK - 1 - ck;
        if (rem >= STAGES-2)  cp_wait<STAGES-2>();
        else if (rem == 3)    cp_wait<3>();
        else if (rem == 2)    cp_wait<2>();
        else if (rem == 1)    cp_wait<1>();
        else                  cp_wait<0>();
        __syncthreads();
        if (ck + STAGES - 1 < NCK)
            issue(ck + STAGES - 1, (ck + STAGES - 1) % STAGES);

        const __half* sA = sm + buf*STAGE_HALVES;
        compute_chunk(sA, sA + SA_BUF, acc, fc);
    }
}

// ---------------- P-table GEMM: [384x2048x256] ----------------
__global__ __launch_bounds__(THREADS, 2) void k_pwg() {
    extern __shared__ __align__(16) __half sm[];
    const int tid = threadIdx.x, lane = tid & 31, wid = tid >> 5;
    const int wm = wid >> 1, wn = wid & 1;
    const int g = lane >> 2, t4 = lane & 3;
    const int col0 = blockIdx.x * BN;
    const int row0 = blockIdx.y * BM;
    const FragCtx fc = { lane & 15, (lane >> 4) << 3,
                         (lane & 7) + ((lane >> 4) << 3), lane & 8, wm, wn };

    float acc[4][8][4];
    #pragma unroll
    for (int mt = 0; mt < 4; mt++)
        #pragma unroll
        for (int nt = 0; nt < 8; nt++)
            #pragma unroll
            for (int q = 0; q < 4; q++) acc[mt][nt][q] = 0.f;

    run_pipeline<CPOL/BK>(sm, g_pfmTh, g_Pw, CPOL, row0, col0, tid, acc, fc);

    const bool isP1 = (blockIdx.x < 8);
    __half* tab = isP1 ? g_P1h : g_P2h;
    #pragma unroll
    for (int mt = 0; mt < 4; mt++) {
        const int r1 = row0 + wm*64 + mt*16 + g;
        const int r2 = r1 + 8;
        #pragma unroll
        for (int nt = 0; nt < 8; nt++) {
            const int n  = col0 + wn*64 + nt*8 + 2*t4;
            const int cl = n & (HID-1);
            float bx = 0.f, by = 0.f;
            if (isP1) {
                float2 bb = *(const float2*)&g_bias1[cl];
                bx = bb.x; by = bb.y;
            }
            if (r1 < BOARD2)
                *(__half2*)&tab[(size_t)r1*HID + cl] =
                    __floats2half2_rn(acc[mt][nt][0] + bx, acc[mt][nt][1] + by);
            if (r2 < BOARD2)
                *(__half2*)&tab[(size_t)r2*HID + cl] =
                    __floats2half2_rn(acc[mt][nt][2] + bx, acc[mt][nt][3] + by);
        }
    }
}

// ---------------- GEMM1: K=64 preload + smem-staged coalesced gather epilogue ----
// h1 = relu(cand@W1c + P1h[go] + P2h[to])
__global__ __launch_bounds__(THREADS, 4) void k_gemm1() {
    extern __shared__ __align__(16) __half sm[];
    const int tid = threadIdx.x, lane = tid & 31, wid = tid >> 5;
    const int wm = wid >> 1, wn = wid & 1;
    const int g = lane >> 2, t4 = lane & 3;
    const int col0 = blockIdx.x * BN;
    const int row0 = blockIdx.y * BM;
    const FragCtx fc = { lane & 15, (lane >> 4) << 3,
                         (lane & 7) + ((lane >> 4) << 3), lane & 8, wm, wn };

    #pragma unroll
    for (int s = 0; s < 2; s++) {
        __half* sA = sm + s*STAGE_HALVES;
        __half* sB = sA + SA_BUF;
        const int k0 = s * BK;
        #pragma unroll
        for (int i = 0; i < 4; i++) {
            int idx = tid + i*THREADS;
            int r = idx >> 2, c4 = idx & 3;
            cpa16(sA + r*SA_STRIDE + c4*8,
                  g_candh + (size_t)(row0 + r)*KCAND + k0 + c4*8);
        }
        #pragma unroll
        for (int i = 0; i < 4; i++) {
            int idx = tid + i*THREADS;
            int r = idx >> 2, c4 = idx & 3;
            cpa16(sB + r*SB_STRIDE + c4*8,
                  g_W1ch + (size_t)(col0 + r)*KCAND + k0 + c4*8);
        }
    }
    CP_COMMIT();

    float acc[4][8][4];
    #pragma unroll
    for (int mt = 0; mt < 4; mt++)
        #pragma unroll
        for (int nt = 0; nt < 8; nt++)
            #pragma unroll
            for (int q = 0; q < 4; q++) acc[mt][nt][q] = 0.f;

    cp_wait<0>();
    __syncthreads();
    compute_chunk(sm, sm + SA_BUF, acc, fc);
    compute_chunk(sm + STAGE_HALVES, sm + STAGE_HALVES + SA_BUF, acc, fc);

    // stage acc tile (fp16) into smem, then row-coalesced gather epilogue
    __syncthreads();                       // all warps done reading stage buffers
    __half* sAcc = sm;                     // 128*ACC_STRIDE halves = 34816 B
    #pragma unroll
    for (int mt = 0; mt < 4; mt++) {
        const int r1l = wm*64 + mt*16 + g;
        const int r2l = r1l + 8;
        #pragma unroll
        for (int nt = 0; nt < 8; nt++) {
            const int c = wn*64 + nt*8 + 2*t4;
            __half2 h01 = __floats2half2_rn(acc[mt][nt][0], acc[mt][nt][1]);
            __half2 h23 = __floats2half2_rn(acc[mt][nt][2], acc[mt][nt][3]);
            *(__half2*)&sAcc[r1l*ACC_STRIDE + c] = h01;
            *(__half2*)&sAcc[r2l*ACC_STRIDE + c] = h23;
        }
    }
    __syncthreads();

    const int R = row0 + tid;              // one row per thread
    const __half* P1r = g_P1h + (size_t)g_go[R]*HID + col0;
    const __half* P2r = g_P2h + (size_t)g_to[R]*HID + col0;
    __half* dst = g_h1 + (size_t)R*HID + col0;
    #pragma unroll 4
    for (int j = 0; j < 16; j++) {
        uint4 av = *(const uint4*)&sAcc[tid*ACC_STRIDE + j*8];
        uint4 p1 = *(const uint4*)(P1r + j*8);
        uint4 p2 = *(const uint4*)(P2r + j*8);
        uint4 o;
        o.x = addrelu2(av.x, p1.x, p2.x);
        o.y = addrelu2(av.y, p1.y, p2.y);
        o.z = addrelu2(av.z, p1.z, p2.z);
        o.w = addrelu2(av.w, p1.w, p2.w);
        *(uint4*)(dst + j*8) = o;
    }
}

// ---------------- GEMM2: K=1024, 5-stage pipeline, fused W3 reduction ----------------
__global__ __launch_bounds__(THREADS, 2) void k_gemm2(
    const float* __restrict__ b2, const float* __restrict__ W3, float* __restrict__ outp)
{
    extern __shared__ __align__(16) __half sm[];
    const int tid = threadIdx.x, lane = tid & 31, wid = tid >> 5;
    const int wm = wid >> 1, wn = wid & 1;
    const int g = lane >> 2, t4 = lane & 3;
    const int col0 = blockIdx.x * BN;
    const int row0 = blockIdx.y * BM;
    const FragCtx fc = { lane & 15, (lane >> 4) << 3,
                         (lane & 7) + ((lane >> 4) << 3), lane & 8, wm, wn };

    float acc[4][8][4];
    #pragma unroll
    for (int mt = 0; mt < 4; mt++)
        #pragma unroll
        for (int nt = 0; nt < 8; nt++)
            #pragma unroll
            for (int q = 0; q < 4; q++) acc[mt][nt][q] = 0.f;

    run_pipeline<HID/BK>(sm, g_h1, g_W2h, HID, row0, col0, tid, acc, fc);

    float rs[4][2];
    #pragma unroll
    for (int mt = 0; mt < 4; mt++) { rs[mt][0] = 0.f; rs[mt][1] = 0.f; }
    #pragma unroll
    for (int nt = 0; nt < 8; nt++) {
        const int c = col0 + wn*64 + nt*8 + 2*t4;
        float2 bb = *(const float2*)&b2[c];
        float2 ww = *(const float2*)&W3[c];
        #pragma unroll
        for (int mt = 0; mt < 4; mt++) {
            rs[mt][0] += fmaxf(acc[mt][nt][0] + bb.x, 0.f)*ww.x
                       + fmaxf(acc[mt][nt][1] + bb.y, 0.f)*ww.y;
            rs[mt][1] += fmaxf(acc[mt][nt][2] + bb.x, 0.f)*ww.x
                       + fmaxf(acc[mt][nt][3] + bb.y, 0.f)*ww.y;
        }
    }
    #pragma unroll
    for (int mt = 0; mt < 4; mt++)
        #pragma unroll
        for (int j = 0; j < 2; j++) {
            float v = rs[mt][j];
            v += __shfl_xor_sync(0xffffffffu, v, 1);
            v += __shfl_xor_sync(0xffffffffu, v, 2);
            if (t4 == 0)
                atomicAdd(outp + row0 + wm*64 + mt*16 + g + 8*j, v);
        }
}

// ---------------- launch ----------------
extern "C" void kernel_launch(void* const* d_in, const int* in_sizes, int n_in,
                              void* d_out, int out_size)
{
    const float* pfm  = (const float*)d_in[0];
    const float* cand = (const float*)d_in[1];
    const float* W1   = (const float*)d_in[2];
    const float* b1   = (const float*)d_in[3];
    const float* W2   = (const float*)d_in[4];
    const float* b2   = (const float*)d_in[5];
    const float* W3   = (const float*)d_in[6];
    const float* b3   = (const float*)d_in[7];
    float* out = (float*)d_out;

    cudaFuncSetAttribute(k_pwg,   cudaFuncAttributeMaxDynamicSharedMemorySize, SMEM_BYTES);
    cudaFuncSetAttribute(k_gemm1, cudaFuncAttributeMaxDynamicSharedMemorySize, SMEM1_BYTES);
    cudaFuncSetAttribute(k_gemm2, cudaFuncAttributeMaxDynamicSharedMemorySize, SMEM_BYTES);

    k_pre<<<PRE_TOTAL, 256>>>(pfm, b1, cand, out, b3, W2, W1);
    k_bias1<<<dim3(HID/128, CPOL/8), 128>>>(W1);
    k_pwg<<<dim3(2048/BN, 384/BM), THREADS, SMEM_BYTES>>>();

    dim3 grid(HID/BN, NCAND/BM);   // (8, 512): col-block fastest
    k_gemm1<<<grid, THREADS, SMEM1_BYTES>>>();
    k_gemm2<<<grid, THREADS, SMEM_BYTES>>>(b2, W3, out);
}

// round 16
// speedup vs baseline: 1.1057x; 1.1057x over previous
#include <cuda_runtime.h>
#include <cuda_fp16.h>

// ---------------- problem constants ----------------
#define NCAND   65536
#define HID     1024
#define BOARD2  361
#define CPOL    256
#define KCAND   64

// ---------------- GEMM tiling (fp16 mma.sync m16n8k16 + ldmatrix) ----------------
#define BM 128
#define BN 128
#define BK 32            // two k16 mma steps per chunk
#define STAGES 5         // pipeline depth
#define THREADS 128
#define SA_STRIDE 40     // halves; 80B row -> LDSM conflict-free
#define SB_STRIDE 40
#define SA_BUF (BM*SA_STRIDE)            // 5120 halves
#define SB_BUF (BN*SB_STRIDE)            // 5120 halves
#define STAGE_HALVES (SA_BUF + SB_BUF)   // 10240
#define SMEM_BYTES (STAGES*STAGE_HALVES*2)   // 102400 (x2 CTAs = 200KB < 228KB)
#define SMEM1_BYTES (2*STAGE_HALVES*2)       // GEMM1: 2 stages = 40960
#define ACC_STRIDE 136                        // staging stride (halves); cf-free writes

// merged-prep block ranges (256 threads each)
#define PRE_PFM   0                       // 256 blocks: pfm transpose + pool + b1 copy
#define PRE_CAND  (PRE_PFM + CPOL)        // 4096 blocks: cand fp16 convert (vec4)
#define PRE_WT    (PRE_CAND + 4096)       // 1600 blocks: W2/W1c/Pw transposes
#define PRE_POS   (PRE_WT + 1600)         // 256 blocks: pos decode + out init
#define PRE_TOTAL (PRE_POS + 256)         // 6208

// ---------------- device scratch ----------------
__device__ float g_pool[CPOL];
__device__ float g_bias1[HID];
__device__ __align__(16) __half g_pfmTh[384*CPOL];  // fp16 pfm^T [p][c], rows 361+ stay zero
__device__ __align__(16) __half g_Pw[2048*CPOL];    // P-GEMM B [n][c]
__device__ __align__(16) __half g_P1h[BOARD2*HID];  // fp16(P1 + bias1)
__device__ __align__(16) __half g_P2h[BOARD2*HID];  // fp16(P2)
__device__ int   g_go[NCAND];
__device__ int   g_to[NCAND];
__device__ __align__(16) __half g_candh[NCAND*KCAND];     // fp16 cand feats [m][64]
__device__ __align__(16) __half g_W1ch[HID*KCAND];        // fp16 W1[768:832]^T [n][k]
__device__ __align__(16) __half g_W2h[HID*HID];           // fp16 W2^T          [n][k]
__device__ __align__(16) __half g_h1[(size_t)NCAND*HID];  // layer-1 activations fp16

// ---------------- helpers ----------------
__device__ __forceinline__ void cpa16(const void* smem_dst, const void* gmem_src) {
    unsigned sa;
    asm("{ .reg .u64 t; cvta.to.shared.u64 t, %1; cvt.u32.u64 %0, t; }"
        : "=r"(sa) : "l"(smem_dst));
    asm volatile("cp.async.cg.shared.global [%0], [%1], 16;" :: "r"(sa), "l"(gmem_src));
}
#define CP_COMMIT() asm volatile("cp.async.commit_group;")
template<int N>
__device__ __forceinline__ void cp_wait() {
    asm volatile("cp.async.wait_group %0;" :: "n"(N));
}

__device__ __forceinline__ void ldsm4(unsigned& r0, unsigned& r1, unsigned& r2, unsigned& r3,
                                      const __half* p) {
    unsigned sa;
    asm("{ .reg .u64 t; cvta.to.shared.u64 t, %1; cvt.u32.u64 %0, t; }"
        : "=r"(sa) : "l"(p));
    asm volatile("ldmatrix.sync.aligned.m8n8.x4.shared.b16 {%0,%1,%2,%3}, [%4];"
        : "=r"(r0), "=r"(r1), "=r"(r2), "=r"(r3) : "r"(sa));
}

__device__ __forceinline__ void mma16(float* c, const unsigned* a, const unsigned* b) {
    asm volatile(
        "mma.sync.aligned.m16n8k16.row.col.f32.f16.f16.f32 "
        "{%0,%1,%2,%3}, {%4,%5,%6,%7}, {%8,%9}, {%0,%1,%2,%3};"
        : "+f"(c[0]), "+f"(c[1]), "+f"(c[2]), "+f"(c[3])
        : "r"(a[0]), "r"(a[1]), "r"(a[2]), "r"(a[3]), "r"(b[0]), "r"(b[1]));
}

// fp16x2 + table1 + table2 in fp32, relu, repack
__device__ __forceinline__ unsigned addrelu2(unsigned a, unsigned p1, unsigned p2) {
    float2 af = __half22float2(*(__half2*)&a);
    float2 f1 = __half22float2(*(__half2*)&p1);
    float2 f2 = __half22float2(*(__half2*)&p2);
    __half2 r = __floats2half2_rn(fmaxf(af.x + f1.x + f2.x, 0.f),
                                  fmaxf(af.y + f1.y + f2.y, 0.f));
    return *(unsigned*)&r;
}

// ---------------- merged prep kernel ----------------
__global__ __launch_bounds__(256) void k_pre(
    const float* __restrict__ pfm, const float* __restrict__ b1,
    const float* __restrict__ cand, float* __restrict__ out,
    const float* __restrict__ b3,
    const float* __restrict__ W2, const float* __restrict__ W1)
{
    __shared__ float sh[32*33];
    const int bx = blockIdx.x;
    const int tid = threadIdx.x;

    if (bx < PRE_CAND) {
        const int c = bx;
        if (tid < 4) g_bias1[c*4 + tid] = b1[c*4 + tid];
        float s = 0.f;
        for (int p = tid; p < BOARD2; p += 256) {
            float v = pfm[c*BOARD2 + p];
            g_pfmTh[p*CPOL + c] = __float2half_rn(v);
            s += v;
        }
        sh[tid] = s; __syncthreads();
        for (int o = 128; o > 0; o >>= 1) {
            if (tid < o) sh[tid] += sh[tid + o];
            __syncthreads();
        }
        if (tid == 0) g_pool[c] = sh[0] / 361.0f;
    } else if (bx < PRE_WT) {
        const int i4 = (bx - PRE_CAND)*256 + tid;
        float4 v = *(const float4*)(cand + (size_t)i4*4);
        __half2 h0 = __floats2half2_rn(v.x, v.y);
        __half2 h1 = __floats2half2_rn(v.z, v.w);
        uint2 o2;
        o2.x = *(unsigned*)&h0;
        o2.y = *(unsigned*)&h1;
        *(uint2*)(g_candh + (size_t)i4*4) = o2;
    } else if (bx < PRE_POS) {
        float (*t)[33] = (float(*)[33])sh;
        const int b2i = bx - PRE_WT;
        const int gx = b2i & 31, gy = b2i >> 5;
        const int bxn = gx*32;
        const int x = tid & 31, y = tid >> 5;
        if (gy < 32) {
            int by = gy*32;
            for (int i = y; i < 32; i += 8)
                t[i][x] = W2[(size_t)(by+i)*HID + bxn + x];
            __syncthreads();
            for (int i = y; i < 32; i += 8)
                g_W2h[(size_t)(bxn+i)*HID + by + x] = __float2half_rn(t[x][i]);
        } else if (gy < 34) {
            int kb = (gy - 32)*32;
            for (int i = y; i < 32; i += 8)
                t[i][x] = W1[(size_t)(768+kb+i)*HID + bxn + x];
            __syncthreads();
            for (int i = y; i < 32; i += 8)
                g_W1ch[(size_t)(bxn+i)*KCAND + kb + x] = __float2half_rn(t[x][i]);
        } else if (gy < 42) {
            int kb = (gy - 34)*32;
            for (int i = y; i < 32; i += 8)
                t[i][x] = W1[(size_t)(kb+i)*HID + bxn + x];
            __syncthreads();
            for (int i = y; i < 32; i += 8)
                g_Pw[(size_t)(bxn+i)*CPOL + kb + x] = __float2half_rn(t[x][i]);
        } else {
            int kb = (gy - 42)*32;
            for (int i = y; i < 32; i += 8)
                t[i][x] = W1[(size_t)(256+kb+i)*HID + bxn + x];
            __syncthreads();
            for (int i = y; i < 32; i += 8)
                g_Pw[(size_t)(1024+bxn+i)*CPOL + kb + x] = __float2half_rn(t[x][i]);
        }
    } else {
        const int i = (bx - PRE_POS)*256 + tid;
        const float* f = cand + (size_t)i*KCAND;
        int gr = min(max((int)(f[5]*18.f), 0), 18);
        int gc = min(max((int)(f[6]*18.f), 0), 18);
        int tr = min(max((int)(f[7]*18.f), 0), 18);
        int tc = min(max((int)(f[8]*18.f), 0), 18);
        g_go[i] = gr*19 + gc;
        g_to[i] = tr*19 + tc;
        out[i] = b3[0];
    }
}

// bias1 += pool @ W1[512:768]   (split-k x32, atomic; fp32, exact)
__global__ void k_bias1(const float* __restrict__ W1) {
    int o  = blockIdx.x*128 + threadIdx.x;
    int c0 = blockIdx.y*8;
    float s = 0.f;
    #pragma unroll
    for (int c = c0; c < c0 + 8; c++)
        s += g_pool[c] * W1[(size_t)(512+c)*HID + o];
    atomicAdd(&g_bias1[o], s);
}

// ---------------- shared mainloop pieces ----------------
struct FragCtx {
    int aRowL, aKL, bNL, bKL, wm, wn;
};

__device__ __forceinline__ void compute_chunk(const __half* sA, const __half* sB,
                                              float acc[4][8][4], const FragCtx& fc) {
    const __half* pA = sA + (fc.wm*64 + fc.aRowL)*SA_STRIDE + fc.aKL;
    const __half* pB = sB + (fc.wn*64 + fc.bNL)*SB_STRIDE + fc.bKL;
    #pragma unroll
    for (int ks = 0; ks < 2; ks++) {
        const int kofs = ks*16;
        unsigned a[4][4], b[8][2];
        #pragma unroll
        for (int mt = 0; mt < 4; mt++)
            ldsm4(a[mt][0], a[mt][1], a[mt][2], a[mt][3],
                  pA + mt*16*SA_STRIDE + kofs);
        #pragma unroll
        for (int np = 0; np < 4; np++)
            ldsm4(b[2*np][0], b[2*np][1], b[2*np+1][0], b[2*np+1][1],
                  pB + np*16*SB_STRIDE + kofs);
        #pragma unroll
        for (int mt = 0; mt < 4; mt++)
            #pragma unroll
            for (int nt = 0; nt < 8; nt++)
                mma16(acc[mt][nt], a[mt], b[nt]);
    }
}

// pipelined mainloop shared by k_pwg / k_gemm2
template<int NCK>
__device__ __forceinline__ void run_pipeline(
    __half* sm, const __half* __restrict__ Ag, const __half* __restrict__ Bg,
    int lda, int row0, int col0, int tid, float acc[4][8][4], const FragCtx& fc)
{
    auto issue = [&](int ck, int s) {
        __half* sA = sm + s*STAGE_HALVES;
        __half* sB = sA + SA_BUF;
        const int k0 = ck * BK;
        #pragma unroll
        for (int i = 0; i < 4; i++) {
            int idx = tid + i*THREADS;
            int r = idx >> 2, c4 = idx & 3;
            cpa16(sA + r*SA_STRIDE + c4*8,
                  Ag + (size_t)(row0 + r)*lda + k0 + c4*8);
        }
        #pragma unroll
        for (int i = 0; i < 4; i++) {
            int idx = tid + i*THREADS;
            int r = idx >> 2, c4 = idx & 3;
            cpa16(sB + r*SB_STRIDE + c4*8,
                  Bg + (size_t)(col0 + r)*lda + k0 + c4*8);
        }
        CP_COMMIT();
    };

    #pragma unroll
    for (int s = 0; s < STAGES-1; s++) issue(s, s);

    for (int ck = 0; ck < NCK; ck++) {
        const int buf = ck % STAGES;
        const int rem = NCK - 1 - ck;
        if (rem >= STAGES-2)  cp_wait<STAGES-2>();
        else if (rem == 3)    cp_wait<3>();
        else if (rem == 2)    cp_wait<2>();
        else if (rem == 1)    cp_wait<1>();
        else                  cp_wait<0>();
        __syncthreads();
        if (ck + STAGES - 1 < NCK)
            issue(ck + STAGES - 1, (ck + STAGES - 1) % STAGES);

        const __half* sA = sm + buf*STAGE_HALVES;
        compute_chunk(sA, sA + SA_BUF, acc, fc);
    }
}

// ---------------- P-table GEMM: [384x2048x256] ----------------
__global__ __launch_bounds__(THREADS, 2) void k_pwg() {
    extern __shared__ __align__(16) __half sm[];
    const int tid = threadIdx.x, lane = tid & 31, wid = tid >> 5;
    const int wm = wid >> 1, wn = wid & 1;
    const int g = lane >> 2, t4 = lane & 3;
    const int col0 = blockIdx.x * BN;
    const int row0 = blockIdx.y * BM;
    const FragCtx fc = { lane & 15, (lane >> 4) << 3,
                         (lane & 7) + ((lane >> 4) << 3), lane & 8, wm, wn };

    float acc[4][8][4];
    #pragma unroll
    for (int mt = 0; mt < 4; mt++)
        #pragma unroll
        for (int nt = 0; nt < 8; nt++)
            #pragma unroll
            for (int q = 0; q < 4; q++) acc[mt][nt][q] = 0.f;

    run_pipeline<CPOL/BK>(sm, g_pfmTh, g_Pw, CPOL, row0, col0, tid, acc, fc);

    const bool isP1 = (blockIdx.x < 8);
    __half* tab = isP1 ? g_P1h : g_P2h;
    #pragma unroll
    for (int mt = 0; mt < 4; mt++) {
        const int r1 = row0 + wm*64 + mt*16 + g;
        const int r2 = r1 + 8;
        #pragma unroll
        for (int nt = 0; nt < 8; nt++) {
            const int n  = col0 + wn*64 + nt*8 + 2*t4;
            const int cl = n & (HID-1);
            float bx = 0.f, by = 0.f;
            if (isP1) {
                float2 bb = *(const float2*)&g_bias1[cl];
                bx = bb.x; by = bb.y;
            }
            if (r1 < BOARD2)
                *(__half2*)&tab[(size_t)r1*HID + cl] =
                    __floats2half2_rn(acc[mt][nt][0] + bx, acc[mt][nt][1] + by);
            if (r2 < BOARD2)
                *(__half2*)&tab[(size_t)r2*HID + cl] =
                    __floats2half2_rn(acc[mt][nt][2] + bx, acc[mt][nt][3] + by);
        }
    }
}

// ---------------- GEMM1: K=64 preload; smem-staged, row-per-WARP coalesced gather ----
// h1 = relu(cand@W1c + P1h[go] + P2h[to])
__global__ __launch_bounds__(THREADS, 4) void k_gemm1() {
    extern __shared__ __align__(16) __half sm[];
    const int tid = threadIdx.x, lane = tid & 31, wid = tid >> 5;
    const int wm = wid >> 1, wn = wid & 1;
    const int g = lane >> 2, t4 = lane & 3;
    const int col0 = blockIdx.x * BN;
    const int row0 = blockIdx.y * BM;
    const FragCtx fc = { lane & 15, (lane >> 4) << 3,
                         (lane & 7) + ((lane >> 4) << 3), lane & 8, wm, wn };

    #pragma unroll
    for (int s = 0; s < 2; s++) {
        __half* sA = sm + s*STAGE_HALVES;
        __half* sB = sA + SA_BUF;
        const int k0 = s * BK;
        #pragma unroll
        for (int i = 0; i < 4; i++) {
            int idx = tid + i*THREADS;
            int r = idx >> 2, c4 = idx & 3;
            cpa16(sA + r*SA_STRIDE + c4*8,
                  g_candh + (size_t)(row0 + r)*KCAND + k0 + c4*8);
        }
        #pragma unroll
        for (int i = 0; i < 4; i++) {
            int idx = tid + i*THREADS;
            int r = idx >> 2, c4 = idx & 3;
            cpa16(sB + r*SB_STRIDE + c4*8,
                  g_W1ch + (size_t)(col0 + r)*KCAND + k0 + c4*8);
        }
    }
    CP_COMMIT();

    float acc[4][8][4];
    #pragma unroll
    for (int mt = 0; mt < 4; mt++)
        #pragma unroll
        for (int nt = 0; nt < 8; nt++)
            #pragma unroll
            for (int q = 0; q < 4; q++) acc[mt][nt][q] = 0.f;

    cp_wait<0>();
    __syncthreads();
    compute_chunk(sm, sm + SA_BUF, acc, fc);
    compute_chunk(sm + STAGE_HALVES, sm + STAGE_HALVES + SA_BUF, acc, fc);

    // stage acc tile (fp16) into smem
    __syncthreads();                       // all warps done reading stage buffers
    __half* sAcc = sm;                     // 128*ACC_STRIDE halves = 34816 B
    #pragma unroll
    for (int mt = 0; mt < 4; mt++) {
        const int r1l = wm*64 + mt*16 + g;
        const int r2l = r1l + 8;
        #pragma unroll
        for (int nt = 0; nt < 8; nt++) {
            const int c = wn*64 + nt*8 + 2*t4;
            __half2 h01 = __floats2half2_rn(acc[mt][nt][0], acc[mt][nt][1]);
            __half2 h23 = __floats2half2_rn(acc[mt][nt][2], acc[mt][nt][3]);
            *(__half2*)&sAcc[r1l*ACC_STRIDE + c] = h01;
            *(__half2*)&sAcc[r2l*ACC_STRIDE + c] = h23;
        }
    }
    __syncthreads();

    // row-per-warp gather: lanes cover the 128-col slice (256B contiguous per access)
    #pragma unroll 4
    for (int rr = 0; rr < 32; rr++) {
        const int rl = wid*32 + rr;                  // local row
        const int R  = row0 + rl;
        const __half* P1r = g_P1h + (size_t)g_go[R]*HID + col0;
        const __half* P2r = g_P2h + (size_t)g_to[R]*HID + col0;
        uint2 av = *(const uint2*)&sAcc[rl*ACC_STRIDE + lane*4];
        uint2 p1 = *(const uint2*)(P1r + lane*4);
        uint2 p2 = *(const uint2*)(P2r + lane*4);
        uint2 o;
        o.x = addrelu2(av.x, p1.x, p2.x);
        o.y = addrelu2(av.y, p1.y, p2.y);
        *(uint2*)(g_h1 + (size_t)R*HID + col0 + lane*4) = o;
    }
}

// ---------------- GEMM2: K=1024, 5-stage pipeline, fused W3 reduction ----------------
__global__ __launch_bounds__(THREADS, 2) void k_gemm2(
    const float* __restrict__ b2, const float* __restrict__ W3, float* __restrict__ outp)
{
    extern __shared__ __align__(16) __half sm[];
    const int tid = threadIdx.x, lane = tid & 31, wid = tid >> 5;
    const int wm = wid >> 1, wn = wid & 1;
    const int g = lane >> 2, t4 = lane & 3;
    const int col0 = blockIdx.x * BN;
    const int row0 = blockIdx.y * BM;
    const FragCtx fc = { lane & 15, (lane >> 4) << 3,
                         (lane & 7) + ((lane >> 4) << 3), lane & 8, wm, wn };

    float acc[4][8][4];
    #pragma unroll
    for (int mt = 0; mt < 4; mt++)
        #pragma unroll
        for (int nt = 0; nt < 8; nt++)
            #pragma unroll
            for (int q = 0; q < 4; q++) acc[mt][nt][q] = 0.f;

    run_pipeline<HID/BK>(sm, g_h1, g_W2h, HID, row0, col0, tid, acc, fc);

    float rs[4][2];
    #pragma unroll
    for (int mt = 0; mt < 4; mt++) { rs[mt][0] = 0.f; rs[mt][1] = 0.f; }
    #pragma unroll
    for (int nt = 0; nt < 8; nt++) {
        const int c = col0 + wn*64 + nt*8 + 2*t4;
        float2 bb = *(const float2*)&b2[c];
        float2 ww = *(const float2*)&W3[c];
        #pragma unroll
        for (int mt = 0; mt < 4; mt++) {
            rs[mt][0] += fmaxf(acc[mt][nt][0] + bb.x, 0.f)*ww.x
                       + fmaxf(acc[mt][nt][1] + bb.y, 0.f)*ww.y;
            rs[mt][1] += fmaxf(acc[mt][nt][2] + bb.x, 0.f)*ww.x
                       + fmaxf(acc[mt][nt][3] + bb.y, 0.f)*ww.y;
        }
    }
    #pragma unroll
    for (int mt = 0; mt < 4; mt++)
        #pragma unroll
        for (int j = 0; j < 2; j++) {
            float v = rs[mt][j];
            v += __shfl_xor_sync(0xffffffffu, v, 1);
            v += __shfl_xor_sync(0xffffffffu, v, 2);
            if (t4 == 0)
                atomicAdd(outp + row0 + wm*64 + mt*16 + g + 8*j, v);
        }
}

// ---------------- launch ----------------
extern "C" void kernel_launch(void* const* d_in, const int* in_sizes, int n_in,
                              void* d_out, int out_size)
{
    const float* pfm  = (const float*)d_in[0];
    const float* cand = (const float*)d_in[1];
    const float* W1   = (const float*)d_in[2];
    const float* b1   = (const float*)d_in[3];
    const float* W2   = (const float*)d_in[4];
    const float* b2   = (const float*)d_in[5];
    const float* W3   = (const float*)d_in[6];
    const float* b3   = (const float*)d_in[7];
    float* out = (float*)d_out;

    cudaFuncSetAttribute(k_pwg,   cudaFuncAttributeMaxDynamicSharedMemorySize, SMEM_BYTES);
    cudaFuncSetAttribute(k_gemm1, cudaFuncAttributeMaxDynamicSharedMemorySize, SMEM1_BYTES);
    cudaFuncSetAttribute(k_gemm2, cudaFuncAttributeMaxDynamicSharedMemorySize, SMEM_BYTES);

    k_pre<<<PRE_TOTAL, 256>>>(pfm, b1, cand, out, b3, W2, W1);
    k_bias1<<<dim3(HID/128, CPOL/8), 128>>>(W1);
    k_pwg<<<dim3(2048/BN, 384/BM), THREADS, SMEM_BYTES>>>();

    dim3 grid(HID/BN, NCAND/BM);   // (8, 512): col-block fastest
    k_gemm1<<<grid, THREADS, SMEM1_BYTES>>>();
    k_gemm2<<<grid, THREADS, SMEM_BYTES>>>(b2, W3, out);
}

// round 17
// speedup vs baseline: 1.1488x; 1.0389x over previous
#include <cuda_runtime.h>
#include <cuda_fp16.h>

// ---------------- problem constants ----------------
#define NCAND   65536
#define HID     1024
#define BOARD2  361
#define CPOL    256
#define KCAND   64

// ---------------- GEMM tiling (fp16 mma.sync m16n8k16 + ldmatrix) ----------------
#define BM 128
#define BN 128
#define BK 32            // two k16 mma steps per chunk
#define STAGES 5         // pipeline depth
#define THREADS 128
#define SA_STRIDE 40     // halves; 80B row -> LDSM conflict-free
#define SB_STRIDE 40
#define SA_BUF (BM*SA_STRIDE)            // 5120 halves
#define SB_BUF (BN*SB_STRIDE)            // 5120 halves
#define STAGE_HALVES (SA_BUF + SB_BUF)   // 10240
#define SMEM_BYTES (STAGES*STAGE_HALVES*2)   // 102400 (x2 CTAs = 200KB < 228KB)
#define SMEM1_BYTES (2*STAGE_HALVES*2)       // GEMM1: 2 stages = 40960
#define ACC_STRIDE 136                        // staging stride (halves)

// merged-prep block ranges (256 threads each)
#define PRE_PFM   0                       // 256 blocks: pfm transpose + pool + b1 copy
#define PRE_CAND  (PRE_PFM + CPOL)        // 4096 blocks: cand fp16 convert (vec4)
#define PRE_WT    (PRE_CAND + 4096)       // 1600 blocks: W2/W1c/Pw transposes
#define PRE_POS   (PRE_WT + 1600)         // 256 blocks: pos decode + out init
#define PRE_TOTAL (PRE_POS + 256)         // 6208

// ---------------- device scratch ----------------
__device__ float g_pool[CPOL];
__device__ float g_bias1[HID];
__device__ __align__(16) __half g_pfmTh[384*CPOL];  // fp16 pfm^T [p][c], rows 361+ stay zero
__device__ __align__(16) __half g_Pw[2048*CPOL];    // P-GEMM B [n][c]
__device__ __align__(16) __half g_P1h[BOARD2*HID];  // fp16(P1 + bias1)
__device__ __align__(16) __half g_P2h[BOARD2*HID];  // fp16(P2)
__device__ int   g_go[NCAND];
__device__ int   g_to[NCAND];
__device__ __align__(16) __half g_candh[NCAND*KCAND];     // fp16 cand feats [m][64]
__device__ __align__(16) __half g_W1ch[HID*KCAND];        // fp16 W1[768:832]^T [n][k]
__device__ __align__(16) __half g_W2h[HID*HID];           // fp16 W2^T          [n][k]
__device__ __align__(16) __half g_h1[(size_t)NCAND*HID];  // layer-1 activations fp16

// ---------------- helpers ----------------
__device__ __forceinline__ void cpa16(const void* smem_dst, const void* gmem_src) {
    unsigned sa;
    asm("{ .reg .u64 t; cvta.to.shared.u64 t, %1; cvt.u32.u64 %0, t; }"
        : "=r"(sa) : "l"(smem_dst));
    asm volatile("cp.async.cg.shared.global [%0], [%1], 16;" :: "r"(sa), "l"(gmem_src));
}
#define CP_COMMIT() asm volatile("cp.async.commit_group;")
template<int N>
__device__ __forceinline__ void cp_wait() {
    asm volatile("cp.async.wait_group %0;" :: "n"(N));
}

__device__ __forceinline__ void ldsm4(unsigned& r0, unsigned& r1, unsigned& r2, unsigned& r3,
                                      const __half* p) {
    unsigned sa;
    asm("{ .reg .u64 t; cvta.to.shared.u64 t, %1; cvt.u32.u64 %0, t; }"
        : "=r"(sa) : "l"(p));
    asm volatile("ldmatrix.sync.aligned.m8n8.x4.shared.b16 {%0,%1,%2,%3}, [%4];"
        : "=r"(r0), "=r"(r1), "=r"(r2), "=r"(r3) : "r"(sa));
}

__device__ __forceinline__ void mma16(float* c, const unsigned* a, const unsigned* b) {
    asm volatile(
        "mma.sync.aligned.m16n8k16.row.col.f32.f16.f16.f32 "
        "{%0,%1,%2,%3}, {%4,%5,%6,%7}, {%8,%9}, {%0,%1,%2,%3};"
        : "+f"(c[0]), "+f"(c[1]), "+f"(c[2]), "+f"(c[3])
        : "r"(a[0]), "r"(a[1]), "r"(a[2]), "r"(a[3]), "r"(b[0]), "r"(b[1]));
}

// fp16x2 + table1 + table2 in fp32, relu, repack
__device__ __forceinline__ unsigned addrelu2(unsigned a, unsigned p1, unsigned p2) {
    float2 af = __half22float2(*(__half2*)&a);
    float2 f1 = __half22float2(*(__half2*)&p1);
    float2 f2 = __half22float2(*(__half2*)&p2);
    __half2 r = __floats2half2_rn(fmaxf(af.x + f1.x + f2.x, 0.f),
                                  fmaxf(af.y + f1.y + f2.y, 0.f));
    return *(unsigned*)&r;
}

// ---------------- merged prep kernel ----------------
__global__ __launch_bounds__(256) void k_pre(
    const float* __restrict__ pfm, const float* __restrict__ b1,
    const float* __restrict__ cand, float* __restrict__ out,
    const float* __restrict__ b3,
    const float* __restrict__ W2, const float* __restrict__ W1)
{
    __shared__ float sh[32*33];
    const int bx = blockIdx.x;
    const int tid = threadIdx.x;

    if (bx < PRE_CAND) {
        const int c = bx;
        if (tid < 4) g_bias1[c*4 + tid] = b1[c*4 + tid];
        float s = 0.f;
        for (int p = tid; p < BOARD2; p += 256) {
            float v = pfm[c*BOARD2 + p];
            g_pfmTh[p*CPOL + c] = __float2half_rn(v);
            s += v;
        }
        sh[tid] = s; __syncthreads();
        for (int o = 128; o > 0; o >>= 1) {
            if (tid < o) sh[tid] += sh[tid + o];
            __syncthreads();
        }
        if (tid == 0) g_pool[c] = sh[0] / 361.0f;
    } else if (bx < PRE_WT) {
        const int i4 = (bx - PRE_CAND)*256 + tid;
        float4 v = *(const float4*)(cand + (size_t)i4*4);
        __half2 h0 = __floats2half2_rn(v.x, v.y);
        __half2 h1 = __floats2half2_rn(v.z, v.w);
        uint2 o2;
        o2.x = *(unsigned*)&h0;
        o2.y = *(unsigned*)&h1;
        *(uint2*)(g_candh + (size_t)i4*4) = o2;
    } else if (bx < PRE_POS) {
        float (*t)[33] = (float(*)[33])sh;
        const int b2i = bx - PRE_WT;
        const int gx = b2i & 31, gy = b2i >> 5;
        const int bxn = gx*32;
        const int x = tid & 31, y = tid >> 5;
        if (gy < 32) {
            int by = gy*32;
            for (int i = y; i < 32; i += 8)
                t[i][x] = W2[(size_t)(by+i)*HID + bxn + x];
            __syncthreads();
            for (int i = y; i < 32; i += 8)
                g_W2h[(size_t)(bxn+i)*HID + by + x] = __float2half_rn(t[x][i]);
        } else if (gy < 34) {
            int kb = (gy - 32)*32;
            for (int i = y; i < 32; i += 8)
                t[i][x] = W1[(size_t)(768+kb+i)*HID + bxn + x];
            __syncthreads();
            for (int i = y; i < 32; i += 8)
                g_W1ch[(size_t)(bxn+i)*KCAND + kb + x] = __float2half_rn(t[x][i]);
        } else if (gy < 42) {
            int kb = (gy - 34)*32;
            for (int i = y; i < 32; i += 8)
                t[i][x] = W1[(size_t)(kb+i)*HID + bxn + x];
            __syncthreads();
            for (int i = y; i < 32; i += 8)
                g_Pw[(size_t)(bxn+i)*CPOL + kb + x] = __float2half_rn(t[x][i]);
        } else {
            int kb = (gy - 42)*32;
            for (int i = y; i < 32; i += 8)
                t[i][x] = W1[(size_t)(256+kb+i)*HID + bxn + x];
            __syncthreads();
            for (int i = y; i < 32; i += 8)
                g_Pw[(size_t)(1024+bxn+i)*CPOL + kb + x] = __float2half_rn(t[x][i]);
        }
    } else {
        const int i = (bx - PRE_POS)*256 + tid;
        const float* f = cand + (size_t)i*KCAND;
        int gr = min(max((int)(f[5]*18.f), 0), 18);
        int gc = min(max((int)(f[6]*18.f), 0), 18);
        int tr = min(max((int)(f[7]*18.f), 0), 18);
        int tc = min(max((int)(f[8]*18.f), 0), 18);
        g_go[i] = gr*19 + gc;
        g_to[i] = tr*19 + tc;
        out[i] = b3[0];
    }
}

// bias1 += pool @ W1[512:768]   (split-k x32, atomic; fp32, exact)
__global__ void k_bias1(const float* __restrict__ W1) {
    int o  = blockIdx.x*128 + threadIdx.x;
    int c0 = blockIdx.y*8;
    float s = 0.f;
    #pragma unroll
    for (int c = c0; c < c0 + 8; c++)
        s += g_pool[c] * W1[(size_t)(512+c)*HID + o];
    atomicAdd(&g_bias1[o], s);
}

// ---------------- shared mainloop pieces ----------------
struct FragCtx {
    int aRowL, aKL, bNL, bKL, wm, wn;
};

__device__ __forceinline__ void compute_chunk(const __half* sA, const __half* sB,
                                              float acc[4][8][4], const FragCtx& fc) {
    const __half* pA = sA + (fc.wm*64 + fc.aRowL)*SA_STRIDE + fc.aKL;
    const __half* pB = sB + (fc.wn*64 + fc.bNL)*SB_STRIDE + fc.bKL;
    #pragma unroll
    for (int ks = 0; ks < 2; ks++) {
        const int kofs = ks*16;
        unsigned a[4][4], b[8][2];
        #pragma unroll
        for (int mt = 0; mt < 4; mt++)
            ldsm4(a[mt][0], a[mt][1], a[mt][2], a[mt][3],
                  pA + mt*16*SA_STRIDE + kofs);
        #pragma unroll
        for (int np = 0; np < 4; np++)
            ldsm4(b[2*np][0], b[2*np][1], b[2*np+1][0], b[2*np+1][1],
                  pB + np*16*SB_STRIDE + kofs);
        #pragma unroll
        for (int mt = 0; mt < 4; mt++)
            #pragma unroll
            for (int nt = 0; nt < 8; nt++)
                mma16(acc[mt][nt], a[mt], b[nt]);
    }
}

// pipelined mainloop shared by k_pwg / k_gemm2
template<int NCK>
__device__ __forceinline__ void run_pipeline(
    __half* sm, const __half* __restrict__ Ag, const __half* __restrict__ Bg,
    int lda, int row0, int col0, int tid, float acc[4][8][4], const FragCtx& fc)
{
    auto issue = [&](int ck, int s) {
        __half* sA = sm + s*STAGE_HALVES;
        __half* sB = sA + SA_BUF;
        const int k0 = ck * BK;
        #pragma unroll
        for (int i = 0; i < 4; i++) {
            int idx = tid + i*THREADS;
            int r = idx >> 2, c4 = idx & 3;
            cpa16(sA + r*SA_STRIDE + c4*8,
                  Ag + (size_t)(row0 + r)*lda + k0 + c4*8);
        }
        #pragma unroll
        for (int i = 0; i < 4; i++) {
            int idx = tid + i*THREADS;
            int r = idx >> 2, c4 = idx & 3;
            cpa16(sB + r*SB_STRIDE + c4*8,
                  Bg + (size_t)(col0 + r)*lda + k0 + c4*8);
        }
        CP_COMMIT();
    };

    #pragma unroll
    for (int s = 0; s < STAGES-1; s++) issue(s, s);

    for (int ck = 0; ck < NCK; ck++) {
        const int buf = ck % STAGES;
        const int rem = NCK - 1 - ck;
        if (rem >= STAGES-2)  cp_wait<STAGES-2>();
        else if (rem == 3)    cp_wait<3>();
        else if (rem == 2)    cp_wait<2>();
        else if (rem == 1)    cp_wait<1>();
        else                  cp_wait<0>();
        __syncthreads();
        if (ck + STAGES - 1 < NCK)
            issue(ck + STAGES - 1, (ck + STAGES - 1) % STAGES);

        const __half* sA = sm + buf*STAGE_HALVES;
        compute_chunk(sA, sA + SA_BUF, acc, fc);
    }
}

// ---------------- P-table GEMM: [384x2048x256] ----------------
__global__ __launch_bounds__(THREADS, 2) void k_pwg() {
    extern __shared__ __align__(16) __half sm[];
    const int tid = threadIdx.x, lane = tid & 31, wid = tid >> 5;
    const int wm = wid >> 1, wn = wid & 1;
    const int g = lane >> 2, t4 = lane & 3;
    const int col0 = blockIdx.x * BN;
    const int row0 = blockIdx.y * BM;
    const FragCtx fc = { lane & 15, (lane >> 4) << 3,
                         (lane & 7) + ((lane >> 4) << 3), lane & 8, wm, wn };

    float acc[4][8][4];
    #pragma unroll
    for (int mt = 0; mt < 4; mt++)
        #pragma unroll
        for (int nt = 0; nt < 8; nt++)
            #pragma unroll
            for (int q = 0; q < 4; q++) acc[mt][nt][q] = 0.f;

    run_pipeline<CPOL/BK>(sm, g_pfmTh, g_Pw, CPOL, row0, col0, tid, acc, fc);

    const bool isP1 = (blockIdx.x < 8);
    __half* tab = isP1 ? g_P1h : g_P2h;
    #pragma unroll
    for (int mt = 0; mt < 4; mt++) {
        const int r1 = row0 + wm*64 + mt*16 + g;
        const int r2 = r1 + 8;
        #pragma unroll
        for (int nt = 0; nt < 8; nt++) {
            const int n  = col0 + wn*64 + nt*8 + 2*t4;
            const int cl = n & (HID-1);
            float bx = 0.f, by = 0.f;
            if (isP1) {
                float2 bb = *(const float2*)&g_bias1[cl];
                bx = bb.x; by = bb.y;
            }
            if (r1 < BOARD2)
                *(__half2*)&tab[(size_t)r1*HID + cl] =
                    __floats2half2_rn(acc[mt][nt][0] + bx, acc[mt][nt][1] + by);
            if (r2 < BOARD2)
                *(__half2*)&tab[(size_t)r2*HID + cl] =
                    __floats2half2_rn(acc[mt][nt][2] + bx, acc[mt][nt][3] + by);
        }
    }
}

// ---------------- GEMM1: K=64 preload; smem-staged, 2-rows-per-warp uint4 gather ----
// h1 = relu(cand@W1c + P1h[go] + P2h[to])
__global__ __launch_bounds__(THREADS, 4) void k_gemm1() {
    extern __shared__ __align__(16) __half sm[];
    const int tid = threadIdx.x, lane = tid & 31, wid = tid >> 5;
    const int wm = wid >> 1, wn = wid & 1;
    const int g = lane >> 2, t4 = lane & 3;
    const int col0 = blockIdx.x * BN;
    const int row0 = blockIdx.y * BM;
    const FragCtx fc = { lane & 15, (lane >> 4) << 3,
                         (lane & 7) + ((lane >> 4) << 3), lane & 8, wm, wn };

    #pragma unroll
    for (int s = 0; s < 2; s++) {
        __half* sA = sm + s*STAGE_HALVES;
        __half* sB = sA + SA_BUF;
        const int k0 = s * BK;
        #pragma unroll
        for (int i = 0; i < 4; i++) {
            int idx = tid + i*THREADS;
            int r = idx >> 2, c4 = idx & 3;
            cpa16(sA + r*SA_STRIDE + c4*8,
                  g_candh + (size_t)(row0 + r)*KCAND + k0 + c4*8);
        }
        #pragma unroll
        for (int i = 0; i < 4; i++) {
            int idx = tid + i*THREADS;
            int r = idx >> 2, c4 = idx & 3;
            cpa16(sB + r*SB_STRIDE + c4*8,
                  g_W1ch + (size_t)(col0 + r)*KCAND + k0 + c4*8);
        }
    }
    CP_COMMIT();

    float acc[4][8][4];
    #pragma unroll
    for (int mt = 0; mt < 4; mt++)
        #pragma unroll
        for (int nt = 0; nt < 8; nt++)
            #pragma unroll
            for (int q = 0; q < 4; q++) acc[mt][nt][q] = 0.f;

    cp_wait<0>();
    __syncthreads();
    compute_chunk(sm, sm + SA_BUF, acc, fc);
    compute_chunk(sm + STAGE_HALVES, sm + STAGE_HALVES + SA_BUF, acc, fc);

    // stage acc tile (fp16) into smem
    __syncthreads();                       // all warps done reading stage buffers
    __half* sAcc = sm;                     // 128*ACC_STRIDE halves = 34816 B
    #pragma unroll
    for (int mt = 0; mt < 4; mt++) {
        const int r1l = wm*64 + mt*16 + g;
        const int r2l = r1l + 8;
        #pragma unroll
        for (int nt = 0; nt < 8; nt++) {
            const int c = wn*64 + nt*8 + 2*t4;
            __half2 h01 = __floats2half2_rn(acc[mt][nt][0], acc[mt][nt][1]);
            __half2 h23 = __floats2half2_rn(acc[mt][nt][2], acc[mt][nt][3]);
            *(__half2*)&sAcc[r1l*ACC_STRIDE + c] = h01;
            *(__half2*)&sAcc[r2l*ACC_STRIDE + c] = h23;
        }
    }
    __syncthreads();

    // 2 rows per warp iter: lanes 0-15 row rl, lanes 16-31 row rl+1; uint4 per lane
    const int hsel = lane >> 4;             // 0/1 -> row within pair
    const int hc   = (lane & 15)*8;         // column base (8 halves = 16B)
    #pragma unroll 8
    for (int it = 0; it < 16; it++) {
        const int rl = wid*32 + it*2 + hsel;         // local row
        const int R  = row0 + rl;
        const __half* P1r = g_P1h + (size_t)g_go[R]*HID + col0 + hc;
        const __half* P2r = g_P2h + (size_t)g_to[R]*HID + col0 + hc;
        uint4 av = *(const uint4*)&sAcc[rl*ACC_STRIDE + hc];
        uint4 p1 = *(const uint4*)P1r;
        uint4 p2 = *(const uint4*)P2r;
        uint4 o;
        o.x = addrelu2(av.x, p1.x, p2.x);
        o.y = addrelu2(av.y, p1.y, p2.y);
        o.z = addrelu2(av.z, p1.z, p2.z);
        o.w = addrelu2(av.w, p1.w, p2.w);
        *(uint4*)(g_h1 + (size_t)R*HID + col0 + hc) = o;
    }
}

// ---------------- GEMM2: K=1024, 5-stage pipeline, fused W3 reduction ----------------
__global__ __launch_bounds__(THREADS, 2) void k_gemm2(
    const float* __restrict__ b2, const float* __restrict__ W3, float* __restrict__ outp)
{
    extern __shared__ __align__(16) __half sm[];
    const int tid = threadIdx.x, lane = tid & 31, wid = tid >> 5;
    const int wm = wid >> 1, wn = wid & 1;
    const int g = lane >> 2, t4 = lane & 3;
    const int col0 = blockIdx.x * BN;
    const int row0 = blockIdx.y * BM;
    const FragCtx fc = { lane & 15, (lane >> 4) << 3,
                         (lane & 7) + ((lane >> 4) << 3), lane & 8, wm, wn };

    float acc[4][8][4];
    #pragma unroll
    for (int mt = 0; mt < 4; mt++)
        #pragma unroll
        for (int nt = 0; nt < 8; nt++)
            #pragma unroll
            for (int q = 0; q < 4; q++) acc[mt][nt][q] = 0.f;

    run_pipeline<HID/BK>(sm, g_h1, g_W2h, HID, row0, col0, tid, acc, fc);

    float rs[4][2];
    #pragma unroll
    for (int mt = 0; mt < 4; mt++) { rs[mt][0] = 0.f; rs[mt][1] = 0.f; }
    #pragma unroll
    for (int nt = 0; nt < 8; nt++) {
        const int c = col0 + wn*64 + nt*8 + 2*t4;
        float2 bb = *(const float2*)&b2[c];
        float2 ww = *(const float2*)&W3[c];
        #pragma unroll
        for (int mt = 0; mt < 4; mt++) {
            rs[mt][0] += fmaxf(acc[mt][nt][0] + bb.x, 0.f)*ww.x
                       + fmaxf(acc[mt][nt][1] + bb.y, 0.f)*ww.y;
            rs[mt][1] += fmaxf(acc[mt][nt][2] + bb.x, 0.f)*ww.x
                       + fmaxf(acc[mt][nt][3] + bb.y, 0.f)*ww.y;
        }
    }
    #pragma unroll
    for (int mt = 0; mt < 4; mt++)
        #pragma unroll
        for (int j = 0; j < 2; j++) {
            float v = rs[mt][j];
            v += __shfl_xor_sync(0xffffffffu, v, 1);
            v += __shfl_xor_sync(0xffffffffu, v, 2);
            if (t4 == 0)
                atomicAdd(outp + row0 + wm*64 + mt*16 + g + 8*j, v);
        }
}

// ---------------- launch ----------------
extern "C" void kernel_launch(void* const* d_in, const int* in_sizes, int n_in,
                              void* d_out, int out_size)
{
    const float* pfm  = (const float*)d_in[0];
    const float* cand = (const float*)d_in[1];
    const float* W1   = (const float*)d_in[2];
    const float* b1   = (const float*)d_in[3];
    const float* W2   = (const float*)d_in[4];
    const float* b2   = (const float*)d_in[5];
    const float* W3   = (const float*)d_in[6];
    const float* b3   = (const float*)d_in[7];
    float* out = (float*)d_out;

    cudaFuncSetAttribute(k_pwg,   cudaFuncAttributeMaxDynamicSharedMemorySize, SMEM_BYTES);
    cudaFuncSetAttribute(k_gemm1, cudaFuncAttributeMaxDynamicSharedMemorySize, SMEM1_BYTES);
    cudaFuncSetAttribute(k_gemm2, cudaFuncAttributeMaxDynamicSharedMemorySize, SMEM_BYTES);

    k_pre<<<PRE_TOTAL, 256>>>(pfm, b1, cand, out, b3, W2, W1);
    k_bias1<<<dim3(HID/128, CPOL/8), 128>>>(W1);
    k_pwg<<<dim3(2048/BN, 384/BM), THREADS, SMEM_BYTES>>>();

    dim3 grid(HID/BN, NCAND/BM);   // (8, 512): col-block fastest
    k_gemm1<<<grid, THREADS, SMEM1_BYTES>>>();
    k_gemm2<<<grid, THREADS, SMEM_BYTES>>>(b2, W3, out);
}